// round 3
// baseline (speedup 1.0000x reference)
#include <cuda_runtime.h>

#define BB   4
#define NN   8000
#define CC   64
#define KK   32
#define DD   9
#define NCLS 13
#define BN   (BB*NN)

#define CAP      320      // per-thread candidate buffer slots
#define TPB_KNN  224      // 7 warps; grid (36,4)=144 blocks ~ 148 SMs
#define ENC_PTS  64       // points per encoder block (4 workers each)

__device__ float  g_G1[BN*CC];
__device__ float  g_G2[BN*CC];
__device__ float4 g_pts[BN];
__device__ int    g_idx[BN*KK];

__device__ __forceinline__ float inf_f() { return __int_as_float(0x7f800000); }

// ---------------------------------------------------------------------------
// Encoder: feats = relu(x@w1+b1)@w2+b2 ; G1 = feats@f1w ; G2 = feats@f2w
// 64 points/block, 4 workers/point (16 channels each). All weight matrices
// staged in dynamic smem once per block -> GEMM reads are broadcast LDS.
// ---------------------------------------------------------------------------
__global__ __launch_bounds__(256) void encoder_kernel(
    const float* __restrict__ x,
    const float* __restrict__ w1, const float* __restrict__ b1v,
    const float* __restrict__ w2, const float* __restrict__ b2v,
    const float* __restrict__ f1w, const float* __restrict__ f2w)
{
    extern __shared__ float es[];
    float* sw1 = es;                    // 9*64   = 576
    float* sw2 = sw1 + DD*CC;           // 4096
    float* sf1 = sw2 + CC*CC;           // 4096
    float* sf2 = sf1 + CC*CC;           // 4096
    float* sh  = sf2 + CC*CC;           // 64*68
    float* sf  = sh  + ENC_PTS*68;      // 64*68
    float* sx  = sf  + ENC_PTS*68;      // 64*12

    int tid = threadIdx.x;
    int p = tid >> 2, t = tid & 3;
    int g0 = blockIdx.x * ENC_PTS;      // grid = BN/ENC_PTS exactly

    // stage weights (float4 cooperative)
    {
        const float4* s1 = (const float4*)w2;
        const float4* s2 = (const float4*)f1w;
        const float4* s3 = (const float4*)f2w;
        float4* d1 = (float4*)sw2;
        float4* d2 = (float4*)sf1;
        float4* d3 = (float4*)sf2;
        #pragma unroll
        for (int k = 0; k < 4; k++) {
            int i = tid + k*256;
            d1[i] = s1[i]; d2[i] = s2[i]; d3[i] = s3[i];
        }
        if (tid < DD*CC/4) ((float4*)sw1)[tid] = ((const float4*)w1)[tid];
    }
    for (int i = tid; i < ENC_PTS*DD; i += 256) {
        int pp = i / DD, d = i % DD;
        sx[pp*12 + d] = x[(g0 + pp)*DD + d];
    }
    __syncthreads();

    int g = g0 + p;
    if (t == 0) {
        float a = sx[p*12+0], b = sx[p*12+1], c = sx[p*12+2];
        g_pts[g] = make_float4(a, b, c, a*a + b*b + c*c);
    }

    float acc[16];

    // layer 1: hidden = relu(x @ w1 + b1)   (9 -> 64)
    {
        const float4* bq = (const float4*)b1v + t*4;
        #pragma unroll
        for (int c4 = 0; c4 < 4; c4++) {
            float4 bv = bq[c4];
            acc[c4*4+0]=bv.x; acc[c4*4+1]=bv.y; acc[c4*4+2]=bv.z; acc[c4*4+3]=bv.w;
        }
        #pragma unroll
        for (int d = 0; d < DD; d++) {
            float xv = sx[p*12 + d];
            const float4* wv = (const float4*)(sw1 + d*CC + t*16);
            #pragma unroll
            for (int c4 = 0; c4 < 4; c4++) {
                float4 w = wv[c4];
                acc[c4*4+0] = fmaf(xv, w.x, acc[c4*4+0]);
                acc[c4*4+1] = fmaf(xv, w.y, acc[c4*4+1]);
                acc[c4*4+2] = fmaf(xv, w.z, acc[c4*4+2]);
                acc[c4*4+3] = fmaf(xv, w.w, acc[c4*4+3]);
            }
        }
        #pragma unroll
        for (int c = 0; c < 16; c++) sh[p*68 + t*16 + c] = fmaxf(acc[c], 0.f);
    }
    __syncthreads();

    // layer 2: feats = hidden @ w2 + b2   (64 -> 64)
    {
        const float4* bq = (const float4*)b2v + t*4;
        #pragma unroll
        for (int c4 = 0; c4 < 4; c4++) {
            float4 bv = bq[c4];
            acc[c4*4+0]=bv.x; acc[c4*4+1]=bv.y; acc[c4*4+2]=bv.z; acc[c4*4+3]=bv.w;
        }
        #pragma unroll 4
        for (int j = 0; j < CC; j++) {
            float hv = sh[p*68 + j];
            const float4* wv = (const float4*)(sw2 + j*CC + t*16);
            #pragma unroll
            for (int c4 = 0; c4 < 4; c4++) {
                float4 w = wv[c4];
                acc[c4*4+0] = fmaf(hv, w.x, acc[c4*4+0]);
                acc[c4*4+1] = fmaf(hv, w.y, acc[c4*4+1]);
                acc[c4*4+2] = fmaf(hv, w.z, acc[c4*4+2]);
                acc[c4*4+3] = fmaf(hv, w.w, acc[c4*4+3]);
            }
        }
        #pragma unroll
        for (int c = 0; c < 16; c++) sf[p*68 + t*16 + c] = acc[c];
    }
    __syncthreads();

    // G1 = feats @ f1w
    {
        #pragma unroll
        for (int c = 0; c < 16; c++) acc[c] = 0.f;
        #pragma unroll 4
        for (int j = 0; j < CC; j++) {
            float fv = sf[p*68 + j];
            const float4* wv = (const float4*)(sf1 + j*CC + t*16);
            #pragma unroll
            for (int c4 = 0; c4 < 4; c4++) {
                float4 w = wv[c4];
                acc[c4*4+0] = fmaf(fv, w.x, acc[c4*4+0]);
                acc[c4*4+1] = fmaf(fv, w.y, acc[c4*4+1]);
                acc[c4*4+2] = fmaf(fv, w.z, acc[c4*4+2]);
                acc[c4*4+3] = fmaf(fv, w.w, acc[c4*4+3]);
            }
        }
        float4* o = (float4*)(g_G1 + g*CC + t*16);
        #pragma unroll
        for (int c4 = 0; c4 < 4; c4++)
            o[c4] = make_float4(acc[c4*4+0], acc[c4*4+1], acc[c4*4+2], acc[c4*4+3]);
    }

    // G2 = feats @ f2w
    {
        #pragma unroll
        for (int c = 0; c < 16; c++) acc[c] = 0.f;
        #pragma unroll 4
        for (int j = 0; j < CC; j++) {
            float fv = sf[p*68 + j];
            const float4* wv = (const float4*)(sf2 + j*CC + t*16);
            #pragma unroll
            for (int c4 = 0; c4 < 4; c4++) {
                float4 w = wv[c4];
                acc[c4*4+0] = fmaf(fv, w.x, acc[c4*4+0]);
                acc[c4*4+1] = fmaf(fv, w.y, acc[c4*4+1]);
                acc[c4*4+2] = fmaf(fv, w.z, acc[c4*4+2]);
                acc[c4*4+3] = fmaf(fv, w.w, acc[c4*4+3]);
            }
        }
        float4* o = (float4*)(g_G2 + g*CC + t*16);
        #pragma unroll
        for (int c4 = 0; c4 < 4; c4++)
            o[c4] = make_float4(acc[c4*4+0], acc[c4*4+1], acc[c4*4+2], acc[c4*4+3]);
    }
}

// ---------------------------------------------------------------------------
// Exact 32-smallest of buf[0..cnt) via 8x4 group-max insert. Returns worst.
// ---------------------------------------------------------------------------
__device__ __noinline__ float compact32(unsigned long long* buf, int cnt,
                                        float* kd, int* ki)
{
    const float INF = inf_f();
    float gm[8];
    #pragma unroll
    for (int i = 0; i < 8; i++) gm[i] = INF;
    #pragma unroll 1
    for (int i = 0; i < KK; i++) { kd[i] = INF; ki[i] = 0; }
    float worst = INF;

    #pragma unroll 1
    for (int tix = 0; tix < cnt; tix++) {
        unsigned long long v = buf[tix];
        float s = __uint_as_float((unsigned)(v >> 32));
        if (s < worst) {
            int id = (int)(unsigned)v;
            int gsel = 0; float gv = gm[0];
            #pragma unroll
            for (int i = 1; i < 8; i++) if (gm[i] > gv) { gv = gm[i]; gsel = i; }
            int base = gsel*4;
            float v0 = kd[base], v1 = kd[base+1], v2 = kd[base+2], v3 = kd[base+3];
            int e = 0; float ev = v0;
            if (v1 > ev) { ev = v1; e = 1; }
            if (v2 > ev) { ev = v2; e = 2; }
            if (v3 > ev) { ev = v3; e = 3; }
            kd[base+e] = s; ki[base+e] = id;
            float ngm = fmaxf(fmaxf(e==0?s:v0, e==1?s:v1),
                              fmaxf(e==2?s:v2, e==3?s:v3));
            #pragma unroll
            for (int i = 0; i < 8; i++) if (i == gsel) gm[i] = ngm;
            float w8 = gm[0];
            #pragma unroll
            for (int i = 1; i < 8; i++) w8 = fmaxf(w8, gm[i]);
            worst = w8;
        }
    }
    #pragma unroll 1
    for (int i = 0; i < KK; i++)
        buf[i] = ((unsigned long long)__float_as_uint(kd[i]) << 32) |
                 (unsigned)ki[i];
    return worst;
}

// ---------------------------------------------------------------------------
// Exact 32-NN. s = |pj|^2 - 2 pi.pj (order-preserving shift of sq-distance).
// Sampled threshold (10th of 500) -> branch-free appends (junk-store trick:
// unconditional STL at buf[cnt], conditional cnt increment), rare exact
// compaction on overflow, exact full-rescan fallback if <32 survivors.
// ---------------------------------------------------------------------------
__global__ __launch_bounds__(TPB_KNN) void knn_kernel() {
    extern __shared__ float4 sp[];
    int b = blockIdx.y;
    for (int j = threadIdx.x; j < NN; j += TPB_KNN) sp[j] = g_pts[b*NN + j];
    __syncthreads();

    int q = blockIdx.x * TPB_KNN + threadIdx.x;
    if (q >= NN) return;

    float4 me = sp[q];
    float mx = -2.f*me.x, my = -2.f*me.y, mz = -2.f*me.z;
    const float INF = inf_f();

    // ---- prepass: T0 = 10th smallest of 500 stride-16 samples ----
    float t[10];
    #pragma unroll
    for (int i = 0; i < 10; i++) t[i] = INF;
    float tw = INF;
    #pragma unroll 1
    for (int k = 0; k < 125; k++) {
        float s4[4];
        #pragma unroll
        for (int u = 0; u < 4; u++) {
            float4 c = sp[k*64 + u*16];
            float s = fmaf(c.x, mx, c.w);
            s = fmaf(c.y, my, s);
            s4[u] = fmaf(c.z, mz, s);
        }
        float mn = fminf(fminf(s4[0], s4[1]), fminf(s4[2], s4[3]));
        if (mn < tw) {
            #pragma unroll
            for (int u = 0; u < 4; u++) {
                float s = s4[u];
                if (s < tw) {
                    int am = 0; float mv = t[0];
                    #pragma unroll
                    for (int i = 1; i < 10; i++) if (t[i] > mv) { mv = t[i]; am = i; }
                    #pragma unroll
                    for (int i = 0; i < 10; i++) if (i == am) t[i] = s;
                    mv = t[0];
                    #pragma unroll
                    for (int i = 1; i < 10; i++) mv = fmaxf(mv, t[i]);
                    tw = mv;
                }
            }
        }
    }

    // ---- main scan ----
    unsigned long long buf[CAP];
    float kd[KK]; int ki[KK];
    float T0 = tw;
    int cnt = 0;

    #pragma unroll 1
    for (int pass = 0; pass < 2; pass++) {
        cnt = 0;
        float thr = T0;
        #pragma unroll 1
        for (int jg = 0; jg < NN/8; jg++) {
            int j0 = jg*8;
            float s[8];
            #pragma unroll
            for (int u = 0; u < 8; u++) {
                float4 c = sp[j0 + u];
                float ss = fmaf(c.x, mx, c.w);
                ss = fmaf(c.y, my, ss);
                s[u] = fmaf(c.z, mz, ss);
            }
            float m01 = fminf(s[0], s[1]), m23 = fminf(s[2], s[3]);
            float m45 = fminf(s[4], s[5]), m67 = fminf(s[6], s[7]);
            float mn = fminf(fminf(m01, m23), fminf(m45, m67));
            if (mn < thr) {
                // branch-free appends: junk stores get overwritten
                #pragma unroll
                for (int u = 0; u < 8; u++) {
                    buf[cnt] = ((unsigned long long)__float_as_uint(s[u]) << 32)
                               | (unsigned)(j0 + u);
                    cnt += (s[u] < thr) ? 1 : 0;
                }
                if (cnt >= CAP - 8) {
                    float w2 = compact32(buf, cnt, kd, ki);
                    thr = fminf(thr, w2);
                    cnt = KK;
                }
            }
        }
        if (cnt >= KK) break;
        T0 = INF;          // exact fallback: rescan everything
    }

    compact32(buf, cnt, kd, ki);
    int* o = g_idx + (b*NN + q)*KK;
    #pragma unroll 1
    for (int i = 0; i < KK; i++) o[i] = ki[i];
}

// ---------------------------------------------------------------------------
// Fuse (both branches) + classifier. msg = relu(G[nbr]-G[i]+b); max over K;
// fused = m1+m2; then 64->32->13 MLP. 4 points/block, 64 channel-threads.
// ---------------------------------------------------------------------------
__global__ __launch_bounds__(256) void fuse_kernel(
    const float* __restrict__ f1b, const float* __restrict__ f2b,
    const float* __restrict__ cw1, const float* __restrict__ cb1,
    const float* __restrict__ cw2, const float* __restrict__ cb2,
    float* __restrict__ out)
{
    __shared__ float sfused[4][CC];
    __shared__ float shid[4][CC/2];
    __shared__ int   sidx[4][KK];

    int tid = threadIdx.x;
    int p = tid >> 6, c = tid & 63;
    int g = blockIdx.x*4 + p;

    if (c < KK) sidx[p][c] = g_idx[g*KK + c];
    __syncthreads();

    int b = g / NN;
    int rowbase = b*NN;

    float g1i = g_G1[g*CC + c];
    float g2i = g_G2[g*CC + c];
    float bb1 = f1b[c] - g1i;
    float bb2 = f2b[c] - g2i;
    float m1 = 0.f, m2 = 0.f;
    #pragma unroll 8
    for (int k = 0; k < KK; k++) {
        int j = sidx[p][k] + rowbase;
        m1 = fmaxf(m1, g_G1[j*CC + c] + bb1);
        m2 = fmaxf(m2, g_G2[j*CC + c] + bb2);
    }
    sfused[p][c] = m1 + m2;
    __syncthreads();

    if (c < CC/2) {
        float a = cb1[c];
        #pragma unroll
        for (int u = 0; u < CC; u++) a = fmaf(sfused[p][u], cw1[u*(CC/2) + c], a);
        shid[p][c] = fmaxf(a, 0.f);
    }
    __syncthreads();

    if (c < NCLS) {
        float a = cb2[c];
        #pragma unroll
        for (int u = 0; u < CC/2; u++) a = fmaf(shid[p][u], cw2[u*NCLS + c], a);
        out[g*NCLS + c] = a;
    }
}

extern "C" void kernel_launch(void* const* d_in, const int* in_sizes, int n_in,
                              void* d_out, int out_size) {
    const float* x      = (const float*)d_in[0];
    const float* enc_w1 = (const float*)d_in[1];
    const float* enc_b1 = (const float*)d_in[2];
    const float* enc_w2 = (const float*)d_in[3];
    const float* enc_b2 = (const float*)d_in[4];
    const float* f1_w   = (const float*)d_in[5];
    const float* f1_b   = (const float*)d_in[6];
    const float* f2_w   = (const float*)d_in[7];
    const float* f2_b   = (const float*)d_in[8];
    const float* cls_w1 = (const float*)d_in[9];
    const float* cls_b1 = (const float*)d_in[10];
    const float* cls_w2 = (const float*)d_in[11];
    const float* cls_b2 = (const float*)d_in[12];

    const int enc_smem = (DD*CC + 3*CC*CC + 2*ENC_PTS*68 + ENC_PTS*12)
                         * (int)sizeof(float);
    cudaFuncSetAttribute(encoder_kernel,
                         cudaFuncAttributeMaxDynamicSharedMemorySize, enc_smem);
    encoder_kernel<<<BN/ENC_PTS, 256, enc_smem>>>(x, enc_w1, enc_b1, enc_w2,
                                                  enc_b2, f1_w, f2_w);

    const int knn_smem = NN * (int)sizeof(float4);   // 128000 B
    cudaFuncSetAttribute(knn_kernel, cudaFuncAttributeMaxDynamicSharedMemorySize,
                         knn_smem);
    dim3 kg((NN + TPB_KNN - 1)/TPB_KNN, BB);
    knn_kernel<<<kg, TPB_KNN, knn_smem>>>();

    fuse_kernel<<<BN/4, 256>>>(f1_b, f2_b, cls_w1, cls_b1, cls_w2, cls_b2,
                               (float*)d_out);
}